// round 1
// baseline (speedup 1.0000x reference)
#include <cuda_runtime.h>
#include <math.h>

#define NP 512
#define ND 3
#define NK 32
#define NT 10
#define NB 8
#define EPSF 1e-6f

// Precomputed per-k constants: (c2, a2h, b2, w_eff), with log2(e) folded in.
__device__ float4 g_kp[NK];
__device__ float  g_cadd;
__device__ float  g_divpart[NB * NP];

__global__ void precompute_kernel(const float* __restrict__ t_in,
                                  const float* __restrict__ mus,
                                  const float* __restrict__ nlg,
                                  const float* __restrict__ mus_t,
                                  const float* __restrict__ nlg_t,
                                  const float* __restrict__ W,
                                  const float* __restrict__ bias,
                                  const float* __restrict__ imp)
{
    if (threadIdx.x != 0) return;
    float t = t_in[0];
    float tr[NT];
    float s = 0.f;
    for (int i = 0; i < NT; i++) {
        float ig  = expf(nlg_t[i]);
        float ig2 = ig * ig;
        float df  = t - mus_t[i];
        float v   = expf(-df * df * ig2);
        tr[i] = v;
        s += v;
    }
    float inv = 1.f / (EPSF + s);
    for (int i = 0; i < NT; i++) tr[i] *= inv;

    float cadd = 0.f;
    for (int i = 0; i < NT; i++) cadd += bias[i] * tr[i];

    const float L = 1.4426950408889634074f;  // log2(e)
    for (int k = 0; k < NK; k++) {
        float w = 0.f;
        for (int i = 0; i < NT; i++) w += W[k * NT + i] * tr[i];
        cadd += imp[k] * imp[k] * w;
        float ig  = expf(nlg[k]);
        float ig2 = ig * ig;
        float mu  = mus[k];
        float4 p;
        p.x = -L * ig2;            // c2
        p.y =  L * ig2 * mu;       // a2h
        p.z = -L * ig2 * mu * mu;  // b2
        p.w =  w;                  // w_eff
        g_kp[k] = p;
    }
    g_cadd = cadd;
}

// One block = one (b, i) target particle; one thread = one source j.
__global__ void __launch_bounds__(NP) pair_kernel(const float* __restrict__ x,
                                                  float* __restrict__ out)
{
    __shared__ float4 kc[NK];
    __shared__ float  red[16][4];

    const int j = threadIdx.x;
    const int i = blockIdx.x;
    const int b = blockIdx.y;

    if (j < NK) kc[j] = g_kp[j];
    __syncthreads();

    const float* xb = x + b * (NP * ND);
    const float xi0 = xb[i * 3 + 0];
    const float xi1 = xb[i * 3 + 1];
    const float xi2 = xb[i * 3 + 2];

    const float rx = xi0 - xb[j * 3 + 0];
    const float ry = xi1 - xb[j * 3 + 1];
    const float rz = xi2 - xb[j * 3 + 2];

    float d2 = fmaf(rx, rx, fmaf(ry, ry, fmaf(rz, rz, EPSF)));
    float d;
    asm("sqrt.approx.ftz.f32 %0, %1;" : "=f"(d) : "f"(d2));

    float s = 0.f, sd = 0.f, sw = 0.f, sdw = 0.f;
#pragma unroll
    for (int k = 0; k < NK; k++) {
        const float4 p = kc[k];
        float drf = fmaf(p.x, d, p.y);           // (L/2) * (-2 ig2 (d-mu))
        float arg = fmaf(drf + p.y, d, p.z);     // -L * ig2 * (d-mu)^2
        float rbf;
        asm("ex2.approx.ftz.f32 %0, %1;" : "=f"(rbf) : "f"(arg));
        float pr = drf * rbf;
        s   += rbf;
        sd  += pr;
        sw   = fmaf(rbf, p.w, sw);
        sdw  = fmaf(pr,  p.w, sdw);
    }

    float den = EPSF + s;
    float inv;
    asm("rcp.approx.ftz.f32 %0, %1;" : "=f"(inv) : "f"(den));

    float swi = sw * inv;
    float fm  = swi + g_cadd;
    const float C = 1.3862943611198906188f;  // 2 * ln 2 (undo the L/2 scaling)
    float dfm = C * inv * fmaf(-swi, sd, sdw);

    if (j == i) { fm = 0.f; dfm = 0.f; }  // remove_diagonal mask

    float fx = rx * fm;
    float fy = ry * fm;
    float fz = rz * fm;
    float dv = fmaf(d, dfm, 3.f * fm);

    // block reduction of (fx, fy, fz, dv) over 512 threads
    const unsigned m = 0xffffffffu;
#pragma unroll
    for (int o = 16; o; o >>= 1) {
        fx += __shfl_down_sync(m, fx, o);
        fy += __shfl_down_sync(m, fy, o);
        fz += __shfl_down_sync(m, fz, o);
        dv += __shfl_down_sync(m, dv, o);
    }
    const int warp = threadIdx.x >> 5;
    const int lane = threadIdx.x & 31;
    if (lane == 0) {
        red[warp][0] = fx; red[warp][1] = fy; red[warp][2] = fz; red[warp][3] = dv;
    }
    __syncthreads();
    if (threadIdx.x < 16) {
        fx = red[threadIdx.x][0];
        fy = red[threadIdx.x][1];
        fz = red[threadIdx.x][2];
        dv = red[threadIdx.x][3];
#pragma unroll
        for (int o = 8; o; o >>= 1) {
            fx += __shfl_down_sync(0xffffu, fx, o);
            fy += __shfl_down_sync(0xffffu, fy, o);
            fz += __shfl_down_sync(0xffffu, fz, o);
            dv += __shfl_down_sync(0xffffu, dv, o);
        }
        if (threadIdx.x == 0) {
            float* fo = out + b * (NP * ND) + i * 3;
            fo[0] = fx; fo[1] = fy; fo[2] = fz;
            g_divpart[b * NP + i] = dv;
        }
    }
}

__global__ void __launch_bounds__(NP) div_reduce_kernel(float* __restrict__ out)
{
    __shared__ float red[16];
    const int b = blockIdx.x;
    float v = g_divpart[b * NP + threadIdx.x];
    const unsigned m = 0xffffffffu;
#pragma unroll
    for (int o = 16; o; o >>= 1) v += __shfl_down_sync(m, v, o);
    const int warp = threadIdx.x >> 5;
    const int lane = threadIdx.x & 31;
    if (lane == 0) red[warp] = v;
    __syncthreads();
    if (threadIdx.x < 16) {
        v = red[threadIdx.x];
#pragma unroll
        for (int o = 8; o; o >>= 1) v += __shfl_down_sync(0xffffu, v, o);
        if (threadIdx.x == 0) out[NB * NP * ND + b] = -v;
    }
}

extern "C" void kernel_launch(void* const* d_in, const int* in_sizes, int n_in,
                              void* d_out, int out_size)
{
    const float* t_in  = (const float*)d_in[0];
    const float* x     = (const float*)d_in[1];
    const float* mus   = (const float*)d_in[2];
    const float* nlg   = (const float*)d_in[3];
    const float* mus_t = (const float*)d_in[4];
    const float* nlg_t = (const float*)d_in[5];
    const float* W     = (const float*)d_in[6];
    const float* bias  = (const float*)d_in[7];
    const float* imp   = (const float*)d_in[8];
    float* out = (float*)d_out;

    precompute_kernel<<<1, 32>>>(t_in, mus, nlg, mus_t, nlg_t, W, bias, imp);
    dim3 grid(NP, NB);
    pair_kernel<<<grid, NP>>>(x, out);
    div_reduce_kernel<<<NB, NP>>>(out);
}

// round 2
// speedup vs baseline: 1.3796x; 1.3796x over previous
#include <cuda_runtime.h>
#include <math.h>

#define NP 512
#define ND 3
#define NK 32
#define NT 10
#define NB 8
#define EPSF 1e-6f

typedef unsigned long long ull;

// Packed per-pair-of-k constants, as float view:
// pair p (k=2p,2p+1): floats [8p+0..1]=c2, [8p+2..3]=a2h, [8p+4..5]=b2, [8p+6..7]=w
__device__ ulonglong2 g_kp2[2 * (NK / 2)];
__device__ float  g_cadd;
__device__ float  g_divpart[NB * NP];

// ---------- f32x2 helpers ----------
__device__ __forceinline__ ull pk2(float lo, float hi) {
    ull r; asm("mov.b64 %0, {%1, %2};" : "=l"(r) : "f"(lo), "f"(hi)); return r;
}
__device__ __forceinline__ void unpk2(ull v, float& lo, float& hi) {
    asm("mov.b64 {%0, %1}, %2;" : "=f"(lo), "=f"(hi) : "l"(v));
}
__device__ __forceinline__ ull fma2(ull a, ull b, ull c) {
    ull r; asm("fma.rn.f32x2 %0, %1, %2, %3;" : "=l"(r) : "l"(a), "l"(b), "l"(c)); return r;
}
__device__ __forceinline__ ull add2(ull a, ull b) {
    ull r; asm("add.rn.f32x2 %0, %1, %2;" : "=l"(r) : "l"(a), "l"(b)); return r;
}
__device__ __forceinline__ ull mul2(ull a, ull b) {
    ull r; asm("mul.rn.f32x2 %0, %1, %2;" : "=l"(r) : "l"(a), "l"(b)); return r;
}

// 32 threads: thread k handles RBF kernel k.
__global__ void precompute_kernel(const float* __restrict__ t_in,
                                  const float* __restrict__ mus,
                                  const float* __restrict__ nlg,
                                  const float* __restrict__ mus_t,
                                  const float* __restrict__ nlg_t,
                                  const float* __restrict__ W,
                                  const float* __restrict__ bias,
                                  const float* __restrict__ imp)
{
    const int k = threadIdx.x;  // 0..31
    const float t = t_in[0];

    // every thread computes the (tiny) time-RBF vector redundantly
    float tr[NT];
    float s = 0.f;
#pragma unroll
    for (int i = 0; i < NT; i++) {
        float ig  = expf(nlg_t[i]);
        float ig2 = ig * ig;
        float df  = t - mus_t[i];
        float v   = expf(-df * df * ig2);
        tr[i] = v;
        s += v;
    }
    const float invs = 1.f / (EPSF + s);
#pragma unroll
    for (int i = 0; i < NT; i++) tr[i] *= invs;

    float w = 0.f;
#pragma unroll
    for (int i = 0; i < NT; i++) w = fmaf(W[k * NT + i], tr[i], w);

    // importance contribution: warp-reduce imp[k]^2 * w
    float v = imp[k] * imp[k] * w;
#pragma unroll
    for (int o = 16; o; o >>= 1) v += __shfl_down_sync(0xffffffffu, v, o);

    const float L = 1.4426950408889634074f;  // log2(e)
    const float ig  = expf(nlg[k]);
    const float ig2 = ig * ig;
    const float mu  = mus[k];
    const float c2  = -L * ig2;
    const float a2h =  L * ig2 * mu;
    const float b2  = -L * ig2 * mu * mu;

    float* f = (float*)g_kp2;
    const int p = k >> 1, h = k & 1;
    f[8 * p + 0 + h] = c2;
    f[8 * p + 2 + h] = a2h;
    f[8 * p + 4 + h] = b2;
    f[8 * p + 6 + h] = w;

    if (k == 0) {
        float cadd = v;
#pragma unroll
        for (int i = 0; i < NT; i++) cadd = fmaf(bias[i], tr[i], cadd);
        g_cadd = cadd;
    }
}

// One block = one (b, i) target particle; one thread = one source j.
__global__ void __launch_bounds__(NP) pair_kernel(const float* __restrict__ x,
                                                  float* __restrict__ out)
{
    __shared__ ulonglong2 kc[NK];      // [2p]={c2,a2h}  [2p+1]={b2,w}
    __shared__ float      red[16][4];

    const int j = threadIdx.x;
    const int i = blockIdx.x;
    const int b = blockIdx.y;

    if (j < NK) kc[j] = g_kp2[j];
    __syncthreads();

    const float* xb = x + b * (NP * ND);
    const float xi0 = xb[i * 3 + 0];
    const float xi1 = xb[i * 3 + 1];
    const float xi2 = xb[i * 3 + 2];

    const float rx = xi0 - xb[j * 3 + 0];
    const float ry = xi1 - xb[j * 3 + 1];
    const float rz = xi2 - xb[j * 3 + 2];

    float d2s = fmaf(rx, rx, fmaf(ry, ry, fmaf(rz, rz, EPSF)));
    float d;
    asm("sqrt.approx.ftz.f32 %0, %1;" : "=f"(d) : "f"(d2s));

    const ull d2 = pk2(d, d);
    ull s2 = 0, sd2 = 0, sw2 = 0, sdw2 = 0;

#pragma unroll
    for (int p = 0; p < NK / 2; p++) {
        const ulonglong2 ca = kc[2 * p];      // c2, a2h
        const ulonglong2 bw = kc[2 * p + 1];  // b2, w
        ull drf2 = fma2(ca.x, d2, ca.y);
        ull tmp2 = add2(drf2, ca.y);
        ull arg2 = fma2(tmp2, d2, bw.x);
        float a0, a1, r0, r1;
        unpk2(arg2, a0, a1);
        asm("ex2.approx.ftz.f32 %0, %1;" : "=f"(r0) : "f"(a0));
        asm("ex2.approx.ftz.f32 %0, %1;" : "=f"(r1) : "f"(a1));
        ull rbf2 = pk2(r0, r1);
        ull pr2  = mul2(drf2, rbf2);
        s2   = add2(s2, rbf2);
        sd2  = add2(sd2, pr2);
        sw2  = fma2(rbf2, bw.y, sw2);
        sdw2 = fma2(pr2,  bw.y, sdw2);
    }

    float sl, sh, sdl, sdh, swl, swh, sdwl, sdwh;
    unpk2(s2, sl, sh);   unpk2(sd2, sdl, sdh);
    unpk2(sw2, swl, swh); unpk2(sdw2, sdwl, sdwh);
    const float s   = sl + sh;
    const float sd  = sdl + sdh;
    const float sw  = swl + swh;
    const float sdw = sdwl + sdwh;

    float inv;
    {
        float den = EPSF + s;
        asm("rcp.approx.ftz.f32 %0, %1;" : "=f"(inv) : "f"(den));
    }

    const float swi = sw * inv;
    float fm  = swi + g_cadd;
    const float C = 1.3862943611198906188f;  // 2 * ln 2
    float dfm = C * inv * fmaf(-swi, sd, sdw);

    if (j == i) { fm = 0.f; dfm = 0.f; }  // remove_diagonal

    float fx = rx * fm;
    float fy = ry * fm;
    float fz = rz * fm;
    float dv = fmaf(d, dfm, 3.f * fm);

    const unsigned m = 0xffffffffu;
#pragma unroll
    for (int o = 16; o; o >>= 1) {
        fx += __shfl_down_sync(m, fx, o);
        fy += __shfl_down_sync(m, fy, o);
        fz += __shfl_down_sync(m, fz, o);
        dv += __shfl_down_sync(m, dv, o);
    }
    const int warp = threadIdx.x >> 5;
    const int lane = threadIdx.x & 31;
    if (lane == 0) {
        red[warp][0] = fx; red[warp][1] = fy; red[warp][2] = fz; red[warp][3] = dv;
    }
    __syncthreads();
    if (threadIdx.x < 16) {
        fx = red[threadIdx.x][0];
        fy = red[threadIdx.x][1];
        fz = red[threadIdx.x][2];
        dv = red[threadIdx.x][3];
#pragma unroll
        for (int o = 8; o; o >>= 1) {
            fx += __shfl_down_sync(0xffffu, fx, o);
            fy += __shfl_down_sync(0xffffu, fy, o);
            fz += __shfl_down_sync(0xffffu, fz, o);
            dv += __shfl_down_sync(0xffffu, dv, o);
        }
        if (threadIdx.x == 0) {
            float* fo = out + b * (NP * ND) + i * 3;
            fo[0] = fx; fo[1] = fy; fo[2] = fz;
            g_divpart[b * NP + i] = dv;
        }
    }
}

__global__ void __launch_bounds__(NP) div_reduce_kernel(float* __restrict__ out)
{
    __shared__ float red[16];
    const int b = blockIdx.x;
    float v = g_divpart[b * NP + threadIdx.x];
    const unsigned m = 0xffffffffu;
#pragma unroll
    for (int o = 16; o; o >>= 1) v += __shfl_down_sync(m, v, o);
    const int warp = threadIdx.x >> 5;
    const int lane = threadIdx.x & 31;
    if (lane == 0) red[warp] = v;
    __syncthreads();
    if (threadIdx.x < 16) {
        v = red[threadIdx.x];
#pragma unroll
        for (int o = 8; o; o >>= 1) v += __shfl_down_sync(0xffffu, v, o);
        if (threadIdx.x == 0) out[NB * NP * ND + b] = -v;
    }
}

extern "C" void kernel_launch(void* const* d_in, const int* in_sizes, int n_in,
                              void* d_out, int out_size)
{
    const float* t_in  = (const float*)d_in[0];
    const float* x     = (const float*)d_in[1];
    const float* mus   = (const float*)d_in[2];
    const float* nlg   = (const float*)d_in[3];
    const float* mus_t = (const float*)d_in[4];
    const float* nlg_t = (const float*)d_in[5];
    const float* W     = (const float*)d_in[6];
    const float* bias  = (const float*)d_in[7];
    const float* imp   = (const float*)d_in[8];
    float* out = (float*)d_out;

    precompute_kernel<<<1, 32>>>(t_in, mus, nlg, mus_t, nlg_t, W, bias, imp);
    dim3 grid(NP, NB);
    pair_kernel<<<grid, NP>>>(x, out);
    div_reduce_kernel<<<NB, NP>>>(out);
}